// round 6
// baseline (speedup 1.0000x reference)
#include <cuda_runtime.h>
#include <cstdint>

// ============================================================================
// out[524288,128] = x @ P^T, P = Sinkhorn(exp(clip((logits+gumbel(u))/3)))
// Fused persistent kernel. Barrier-free streaming GEMM:
//   - P fragments in smem (64 KB), sinkhorn computed per-CTA in prologue
//   - A fragments loaded DIRECTLY from gmem (LDG, L1-cached), no x staging,
//     no cp.async, no mainloop barriers; depth-4 ring prefetch (16%4==0 so the
//     ring phase is tile-invariant -- the R5 depth-3 ring was the correctness bug)
//   - 512 threads = 16 warps (8 wm x 2 wn), warp tile m32 x n64, CTA tile 256x128
// tf32 mma.sync (tcgen05 unavailable: harness targets compute_103, not 103a).
// ============================================================================

#define EPSF 1e-20f

static constexpr int PF_FLOATS = 16384;   // P in B-fragment order
static constexpr int A_FLOATS  = 16384;   // sinkhorn scratch
static constexpr int SMEM_BYTES = (PF_FLOATS + A_FLOATS + 256) * 4;  // 132096

__global__ void __launch_bounds__(512, 1)
fused_kernel(const float* __restrict__ x,
             const float* __restrict__ logits,
             const float* __restrict__ u,
             float* __restrict__ out, int ntiles) {
    extern __shared__ float sh[];
    float*  PF  = sh;                 // 16384
    float*  A   = sh + PF_FLOATS;     // 16384
    float*  Rv  = A + A_FLOATS;       // 128
    float*  Cv  = Rv + 128;           // 128
    float2* PF2 = reinterpret_cast<float2*>(PF);

    const int tid  = threadIdx.x;
    const int lane = tid & 31;
    const int wid  = tid >> 5;
    const int wm   = wid & 7;         // m offset wm*32 within 256-row CTA tile
    const int wn   = wid >> 3;        // n offset wn*64

    // ================= sinkhorn prologue (proven R3 scheme) ==================
    {
        for (int idx = tid; idx < 16384; idx += 512) {
            float uv = u[idx];
            float g  = -logf(-logf(uv + EPSF) + EPSF);
            float la = (logits[idx] + g) * (1.0f / 3.0f);
            la = fminf(10.0f, fmaxf(-10.0f, la));
            A[idx] = expf(la);
        }
        if (tid < 128) Cv[tid] = 1.0f;
        __syncthreads();

        const int i = tid >> 2;   // row/col 0..127
        const int s = tid & 3;

        float4 a4[8];
        float  at[32];
#pragma unroll
        for (int k = 0; k < 8; k++)
            a4[k] = *reinterpret_cast<const float4*>(&A[i * 128 + k * 16 + s * 4]);
#pragma unroll
        for (int k = 0; k < 8; k++)
#pragma unroll
            for (int e = 0; e < 4; e++)
                at[k * 4 + e] = A[(k * 16 + s * 4 + e) * 128 + i];

        for (int it = 0; it < 20; it++) {
            float sum = 0.0f;
#pragma unroll
            for (int k = 0; k < 8; k++) {
                float4 cv = *reinterpret_cast<const float4*>(&Cv[k * 16 + s * 4]);
                sum += a4[k].x * cv.x + a4[k].y * cv.y + a4[k].z * cv.z + a4[k].w * cv.w;
            }
            sum += __shfl_xor_sync(0xffffffffu, sum, 1);
            sum += __shfl_xor_sync(0xffffffffu, sum, 2);
            if (s == 0) Rv[i] = 1.0f / sum;
            __syncthreads();

            float sum2 = 0.0f;
#pragma unroll
            for (int k = 0; k < 8; k++) {
                float4 rv = *reinterpret_cast<const float4*>(&Rv[k * 16 + s * 4]);
                sum2 += at[k * 4 + 0] * rv.x + at[k * 4 + 1] * rv.y +
                        at[k * 4 + 2] * rv.z + at[k * 4 + 3] * rv.w;
            }
            sum2 += __shfl_xor_sync(0xffffffffu, sum2, 1);
            sum2 += __shfl_xor_sync(0xffffffffu, sum2, 2);
            if (s == 0) Cv[i] = 1.0f / sum2;
            __syncthreads();
        }

        // P = diag(r) A diag(c) * (1+2^-11)  [RZ-truncation compensation],
        // tf32-rounded, scattered to B-fragment order.
        const float comp = 1.0f + 0.00048828125f;
        for (int idx = tid; idx < 16384; idx += 512) {
            int n = idx >> 7, k = idx & 127;
            float p = Rv[n] * A[n * 128 + k] * Cv[k] * comp;
            float pt;
            asm("cvt.rna.tf32.f32 %0, %1;" : "=f"(pt) : "f"(p));
            int ss = k >> 3, ko = k & 7;
            int fi = ((ss * 16 + (n >> 3)) * 32 + (n & 7) * 4 + (ko & 3)) * 2 + (ko >> 2);
            PF[fi] = pt;
        }
        __syncthreads();   // PF ready; last sync of the kernel
    }

    // ================= barrier-free streaming mainloop =======================
    const int grid = gridDim.x;
    const int rbase = wm * 32 + (lane >> 2);     // within-tile row for mf=0
    const int cbase = lane & 3;

    int t = blockIdx.x;
    if (t >= ntiles) return;

    const float* xb = x + (size_t)t * 256 * 128;
    uint32_t af[4][8];                // depth-4 ring: slot (s+2)%4 written, s%4 read

    // preload s = 0, 1 of first tile into slots 0, 1
#pragma unroll
    for (int s = 0; s < 2; s++) {
#pragma unroll
        for (int mf = 0; mf < 2; mf++) {
            const float* p0 = xb + (size_t)(rbase + mf * 16) * 128 + s * 8 + cbase;
            af[s][mf * 4 + 0] = __float_as_uint(p0[0]);
            af[s][mf * 4 + 1] = __float_as_uint(p0[8 * 128]);
            af[s][mf * 4 + 2] = __float_as_uint(p0[4]);
            af[s][mf * 4 + 3] = __float_as_uint(p0[8 * 128 + 4]);
        }
    }

    for (; t < ntiles; t += grid) {
        const float* xnext = x + (size_t)(t + grid) * 256 * 128;
        const bool has_next = (t + grid) < ntiles;

        float acc[2][8][4];
#pragma unroll
        for (int mf = 0; mf < 2; mf++)
#pragma unroll
            for (int nt = 0; nt < 8; nt++)
#pragma unroll
                for (int q = 0; q < 4; q++) acc[mf][nt][q] = 0.0f;

#pragma unroll
        for (int s = 0; s < 16; s++) {
            // prefetch fragments for sequence position s+2 into slot (s+2)%4;
            // for s>=14 this wraps into the NEXT tile's s-14 -> slots 0,1,
            // exactly where the next tile iteration reads them (16%4==0).
            {
                int sp = s + 2;
                const float* base = (sp < 16) ? xb : (has_next ? xnext : xb);
                int  se  = (sp < 16) ? sp : (sp - 16);
#pragma unroll
                for (int mf = 0; mf < 2; mf++) {
                    const float* p0 = base + (size_t)(rbase + mf * 16) * 128 + se * 8 + cbase;
                    af[sp % 4][mf * 4 + 0] = __float_as_uint(p0[0]);
                    af[sp % 4][mf * 4 + 1] = __float_as_uint(p0[8 * 128]);
                    af[sp % 4][mf * 4 + 2] = __float_as_uint(p0[4]);
                    af[sp % 4][mf * 4 + 3] = __float_as_uint(p0[8 * 128 + 4]);
                }
            }

            float2 b[8];
#pragma unroll
            for (int nt = 0; nt < 8; nt++)
                b[nt] = PF2[(s * 16 + wn * 8 + nt) * 32 + lane];

            const uint32_t* a = af[s % 4];
#pragma unroll
            for (int mf = 0; mf < 2; mf++) {
#pragma unroll
                for (int nt = 0; nt < 8; nt++) {
                    asm volatile(
                        "mma.sync.aligned.m16n8k8.row.col.f32.tf32.tf32.f32 "
                        "{%0,%1,%2,%3}, {%4,%5,%6,%7}, {%8,%9}, {%0,%1,%2,%3};"
                        : "+f"(acc[mf][nt][0]), "+f"(acc[mf][nt][1]),
                          "+f"(acc[mf][nt][2]), "+f"(acc[mf][nt][3])
                        : "r"(a[mf * 4 + 0]), "r"(a[mf * 4 + 1]),
                          "r"(a[mf * 4 + 2]), "r"(a[mf * 4 + 3]),
                          "r"(__float_as_uint(b[nt].x)), "r"(__float_as_uint(b[nt].y)));
                }
            }
        }

        // epilogue: direct STG.64 (each quad = one 32B sector)
        float2* og = reinterpret_cast<float2*>(out) + (size_t)t * 256 * 64;
#pragma unroll
        for (int mf = 0; mf < 2; mf++) {
            int r0 = wm * 32 + mf * 16 + (lane >> 2);
#pragma unroll
            for (int nt = 0; nt < 8; nt++) {
                int colp = wn * 32 + nt * 4 + (lane & 3);
                og[(size_t)r0 * 64 + colp]       = make_float2(acc[mf][nt][0], acc[mf][nt][1]);
                og[(size_t)(r0 + 8) * 64 + colp] = make_float2(acc[mf][nt][2], acc[mf][nt][3]);
            }
        }

        xb = xnext;
    }
}

// ---------------------------------------------------------------------------
extern "C" void kernel_launch(void* const* d_in, const int* in_sizes, int n_in,
                              void* d_out, int out_size) {
    const float* x      = (const float*)d_in[0];
    const float* logits = (const float*)d_in[1];
    const float* u      = (const float*)d_in[2];
    float*       out    = (float*)d_out;

    int dev = 0, sms = 148;
    cudaGetDevice(&dev);
    cudaDeviceGetAttribute(&sms, cudaDevAttrMultiProcessorCount, dev);

    cudaFuncSetAttribute(fused_kernel, cudaFuncAttributeMaxDynamicSharedMemorySize, SMEM_BYTES);

    int rows   = in_sizes[0] / 128;   // 524288
    int ntiles = rows / 256;          // 2048
    fused_kernel<<<sms, 512, SMEM_BYTES>>>(x, logits, u, out, ntiles);
}

// round 7
// speedup vs baseline: 1.6785x; 1.6785x over previous
#include <cuda_runtime.h>
#include <cstdint>

// ============================================================================
// out[524288,128] = x @ P^T, P = Sinkhorn(exp(clip((logits+gumbel(u))/3)))
// Fused persistent kernel (R2 architecture + K-step register pipeline):
//   - 256 threads = 8 warps (4 wm x 2 wn), warp tile m32 x n64, CTA tile 128x128
//   - x tiles double-buffered via cp.async.cg (coalesced float4 -> smem)
//   - P fragments in smem (fragment order), sinkhorn fused as per-CTA prologue
//   - NEW: depth-2 register ring prefetching next K-step's A/B fragments from
//     smem while current step's 16 MMAs issue (hides 29-cyc LDS latency)
// tf32 mma.sync (tcgen05 unavailable: harness targets compute_103, not 103a).
// ============================================================================

#define EPSF 1e-20f

__device__ __forceinline__ uint32_t smem_u32(const void* p) {
    uint32_t a;
    asm("{ .reg .u64 t; cvta.to.shared.u64 t, %1; cvt.u32.u64 %0, t; }" : "=r"(a) : "l"(p));
    return a;
}
__device__ __forceinline__ void cp16(float* dst, const float* src) {
    uint32_t d = smem_u32(dst);
    asm volatile("cp.async.cg.shared.global [%0], [%1], 16;" :: "r"(d), "l"(src) : "memory");
}
__device__ __forceinline__ void cp_commit() { asm volatile("cp.async.commit_group;" ::: "memory"); }
__device__ __forceinline__ void cp_wait1()  { asm volatile("cp.async.wait_group 1;" ::: "memory"); }

// smem plan (201,728 B): PF 16384 f | XS0 128*132 f | XS1 128*132 f | Rv,Cv 256 f
static constexpr int XS_STRIDE  = 132;
static constexpr int XS_WORDS   = 128 * XS_STRIDE;
static constexpr int PF_FLOATS  = 16384;
static constexpr int SMEM_BYTES = (PF_FLOATS + 2 * XS_WORDS + 256) * 4;

__global__ void __launch_bounds__(256, 1)
fused_kernel(const float* __restrict__ x,
             const float* __restrict__ logits,
             const float* __restrict__ u,
             float* __restrict__ out, int ntiles) {
    extern __shared__ float sh[];
    float*  PF  = sh;
    float*  XS0 = sh + PF_FLOATS;
    float*  XS1 = XS0 + XS_WORDS;
    float*  Rv  = XS1 + XS_WORDS;   // 128
    float*  Cv  = Rv + 128;         // 128
    float2* PF2 = reinterpret_cast<float2*>(PF);

    const int tid  = threadIdx.x;
    const int lane = tid & 31;
    const int wid  = tid >> 5;
    const int wm   = wid & 3;       // m offset wm*32
    const int wn   = wid >> 2;      // n offset wn*64

    const int grid = gridDim.x;
    int t = blockIdx.x;

    // ---- prefetch first x tile into XS0 (hidden under sinkhorn) ----
    if (t < ntiles) {
        const float4* g = reinterpret_cast<const float4*>(x) + (size_t)t * 4096;
#pragma unroll
        for (int i = 0; i < 16; i++) {
            int f4 = i * 256 + tid;
            int m = f4 >> 5, c4 = f4 & 31;
            cp16(XS0 + m * XS_STRIDE + c4 * 4, reinterpret_cast<const float*>(g + f4));
        }
    }
    cp_commit();   // group for tile t

    // ================= sinkhorn prologue (A in XS1; proven 256-thr scheme) ===
    {
        float* A = XS1;
        for (int idx = tid; idx < 16384; idx += 256) {
            float uv = u[idx];
            float g  = -logf(-logf(uv + EPSF) + EPSF);
            float la = (logits[idx] + g) * (1.0f / 3.0f);
            la = fminf(10.0f, fmaxf(-10.0f, la));
            A[idx] = expf(la);
        }
        if (tid < 128) Cv[tid] = 1.0f;
        __syncthreads();

        const int i = tid >> 1;     // row/col 0..127
        const int s = tid & 1;      // half selector

        float4 a4[16];              // row i, cols [s*64, s*64+64)
        float  at[64];              // col i, rows [s*64, s*64+64)
#pragma unroll
        for (int k = 0; k < 16; k++)
            a4[k] = *reinterpret_cast<const float4*>(&A[i * 128 + s * 64 + k * 4]);
#pragma unroll
        for (int j = 0; j < 64; j++)
            at[j] = A[(s * 64 + j) * 128 + i];

        for (int it = 0; it < 20; it++) {
            float sum = 0.0f;
#pragma unroll
            for (int k = 0; k < 16; k++) {
                float4 cv = *reinterpret_cast<const float4*>(&Cv[s * 64 + k * 4]);
                sum += a4[k].x * cv.x + a4[k].y * cv.y + a4[k].z * cv.z + a4[k].w * cv.w;
            }
            sum += __shfl_xor_sync(0xffffffffu, sum, 1);
            if (s == 0) Rv[i] = 1.0f / sum;
            __syncthreads();

            float sum2 = 0.0f;
#pragma unroll
            for (int j = 0; j < 64; j += 4) {
                float4 rv = *reinterpret_cast<const float4*>(&Rv[s * 64 + j]);
                sum2 += at[j] * rv.x + at[j + 1] * rv.y + at[j + 2] * rv.z + at[j + 3] * rv.w;
            }
            sum2 += __shfl_xor_sync(0xffffffffu, sum2, 1);
            if (s == 0) Cv[i] = 1.0f / sum2;
            __syncthreads();
        }

        // P = diag(r) A diag(c) * (1+2^-11) [mma RZ-truncation compensation],
        // tf32-rounded, scattered into B-fragment order:
        //   PF2[(ss*16+nt)*32+lane] = {P[n][k0], P[n][k0+4]},
        //   n = nt*8 + (lane>>2), k0 = ss*8 + (lane&3).
        const float comp = 1.0f + 0.00048828125f;
        for (int idx = tid; idx < 16384; idx += 256) {
            int n = idx >> 7, k = idx & 127;
            float p = Rv[n] * A[n * 128 + k] * Cv[k] * comp;
            float pt;
            asm("cvt.rna.tf32.f32 %0, %1;" : "=f"(pt) : "f"(p));
            int ss = k >> 3, ko = k & 7;
            int fi = ((ss * 16 + (n >> 3)) * 32 + (n & 7) * 4 + (ko & 3)) * 2 + (ko >> 2);
            PF[fi] = pt;
        }
        __syncthreads();   // A (XS1) dead; PF ready
    }

    // ================= persistent GEMM mainloop ==============================
    float* buf[2] = {XS0, XS1};
    int cur = 0;

    const int arow = wm * 32 + (lane >> 2);   // mf=0 fragment row
    const int acol = lane & 3;

    for (; t < ntiles; t += grid) {
        // issue next tile into the other buffer (overlaps this tile's compute)
        int tn = t + grid;
        if (tn < ntiles) {
            const float4* g = reinterpret_cast<const float4*>(x) + (size_t)tn * 4096;
            float* xb = buf[cur ^ 1];
#pragma unroll
            for (int i = 0; i < 16; i++) {
                int f4 = i * 256 + tid;
                int m = f4 >> 5, c4 = f4 & 31;
                cp16(xb + m * XS_STRIDE + c4 * 4, reinterpret_cast<const float*>(g + f4));
            }
        }
        cp_commit();
        cp_wait1();            // tile t's group complete
        __syncthreads();

        const float* X = buf[cur];

        float acc[2][8][4];
#pragma unroll
        for (int mf = 0; mf < 2; mf++)
#pragma unroll
            for (int nt = 0; nt < 8; nt++)
#pragma unroll
                for (int q = 0; q < 4; q++) acc[mf][nt][q] = 0.0f;

        // depth-2 register ring over K-steps
        float2   bf[2][8];
        uint32_t af[2][8];

#define PREFETCH_FRAGS(S, SLOT)                                                  \
        {                                                                        \
            _Pragma("unroll")                                                    \
            for (int nt = 0; nt < 8; nt++)                                       \
                bf[SLOT][nt] = PF2[((S) * 16 + wn * 8 + nt) * 32 + lane];        \
            _Pragma("unroll")                                                    \
            for (int mf = 0; mf < 2; mf++) {                                     \
                const float* p0 = X + (arow + mf * 16) * XS_STRIDE + (S) * 8 + acol; \
                af[SLOT][mf * 4 + 0] = __float_as_uint(p0[0]);                   \
                af[SLOT][mf * 4 + 1] = __float_as_uint(p0[8 * XS_STRIDE]);       \
                af[SLOT][mf * 4 + 2] = __float_as_uint(p0[4]);                   \
                af[SLOT][mf * 4 + 3] = __float_as_uint(p0[8 * XS_STRIDE + 4]);   \
            }                                                                    \
        }

        PREFETCH_FRAGS(0, 0);

#pragma unroll
        for (int s = 0; s < 16; s++) {
            if (s < 15) PREFETCH_FRAGS(s + 1, (s + 1) & 1);

            const uint32_t* a = af[s & 1];
            const float2*   b = bf[s & 1];
#pragma unroll
            for (int mf = 0; mf < 2; mf++) {
#pragma unroll
                for (int nt = 0; nt < 8; nt++) {
                    asm volatile(
                        "mma.sync.aligned.m16n8k8.row.col.f32.tf32.tf32.f32 "
                        "{%0,%1,%2,%3}, {%4,%5,%6,%7}, {%8,%9}, {%0,%1,%2,%3};"
                        : "+f"(acc[mf][nt][0]), "+f"(acc[mf][nt][1]),
                          "+f"(acc[mf][nt][2]), "+f"(acc[mf][nt][3])
                        : "r"(a[mf * 4 + 0]), "r"(a[mf * 4 + 1]),
                          "r"(a[mf * 4 + 2]), "r"(a[mf * 4 + 3]),
                          "r"(__float_as_uint(b[nt].x)), "r"(__float_as_uint(b[nt].y)));
                }
            }
        }
#undef PREFETCH_FRAGS

        // ---- epilogue: direct STG.64 (each quad = one 32B sector) ----
        float2* og = reinterpret_cast<float2*>(out) + (size_t)t * 128 * 64;
#pragma unroll
        for (int mf = 0; mf < 2; mf++) {
            int r0 = wm * 32 + mf * 16 + (lane >> 2);
#pragma unroll
            for (int nt = 0; nt < 8; nt++) {
                int colp = wn * 32 + nt * 4 + (lane & 3);
                og[(size_t)r0 * 64 + colp]       = make_float2(acc[mf][nt][0], acc[mf][nt][1]);
                og[(size_t)(r0 + 8) * 64 + colp] = make_float2(acc[mf][nt][2], acc[mf][nt][3]);
            }
        }
        __syncthreads();   // all warps done with buf[cur] before it is refilled
        cur ^= 1;
    }
}

// ---------------------------------------------------------------------------
extern "C" void kernel_launch(void* const* d_in, const int* in_sizes, int n_in,
                              void* d_out, int out_size) {
    const float* x      = (const float*)d_in[0];
    const float* logits = (const float*)d_in[1];
    const float* u      = (const float*)d_in[2];
    float*       out    = (float*)d_out;

    int dev = 0, sms = 148;
    cudaGetDevice(&dev);
    cudaDeviceGetAttribute(&sms, cudaDevAttrMultiProcessorCount, dev);

    cudaFuncSetAttribute(fused_kernel, cudaFuncAttributeMaxDynamicSharedMemorySize, SMEM_BYTES);

    int rows   = in_sizes[0] / 128;   // 524288
    int ntiles = rows / 128;          // 4096
    fused_kernel<<<sms, 256, SMEM_BYTES>>>(x, logits, u, out, ntiles);
}

// round 9
// speedup vs baseline: 2.0281x; 1.2083x over previous
#include <cuda_runtime.h>
#include <cstdint>

// ============================================================================
// out[524288,128] = x @ P^T, P = Sinkhorn(exp(clip((logits+gumbel(u))/3)))
// Fused persistent kernel. Warp-pair pipelines:
//   - 256 threads = 8 warps = 4 independent pairs (wm 0..3); pair = {wn0, wn1}
//   - each pair owns a 32-row band of the 128-row CTA tile and TWO private
//     8 KB k-half slots (32 rows x 64 cols, XOR-swizzled, conflict-free)
//   - cp.async + cp.async.mbarrier.arrive.noinc signals slot readiness;
//     consumers wait mbarrier parity. NO CTA-wide barriers in the mainloop.
//   - warp tile m32 x n64, tf32 mma.sync; P fragments in smem; fused sinkhorn
//   R8 bug fixed: within-pair index is (wn<<5)|lane (pair warps are wid and
//   wid+4, NOT tid-adjacent; tid&63 left half of each slot unfilled).
// (tcgen05 unavailable: harness targets compute_103, not 103a.)
// ============================================================================

#define EPSF 1e-20f

__device__ __forceinline__ uint32_t smem_u32(const void* p) {
    uint32_t a;
    asm("{ .reg .u64 t; cvta.to.shared.u64 t, %1; cvt.u32.u64 %0, t; }" : "=r"(a) : "l"(p));
    return a;
}
__device__ __forceinline__ void cp16(float* dst, const float* src) {
    uint32_t d = smem_u32(dst);
    asm volatile("cp.async.cg.shared.global [%0], [%1], 16;" :: "r"(d), "l"(src) : "memory");
}
__device__ __forceinline__ void cp_arrive(uint32_t mb) {
    asm volatile("cp.async.mbarrier.arrive.noinc.shared::cta.b64 [%0];" :: "r"(mb) : "memory");
}
__device__ __forceinline__ void mbar_init(uint32_t mb, uint32_t cnt) {
    asm volatile("mbarrier.init.shared.b64 [%0], %1;" :: "r"(mb), "r"(cnt) : "memory");
}
__device__ __forceinline__ void mbar_wait(uint32_t mb, int parity) {
    asm volatile(
        "{\n\t.reg .pred P;\n"
        "W%=:\n\tmbarrier.try_wait.parity.acquire.cta.shared::cta.b64 P, [%0], %1, 0x989680;\n"
        "\t@P bra D%=;\n\tbra W%=;\n"
        "D%=:\n\t}"
        :: "r"(mb), "r"(parity) : "memory");
}
__device__ __forceinline__ void pair_bar(int id) {
    asm volatile("bar.sync %0, 64;" :: "r"(id) : "memory");
}

// smem plan: PF 16384 f | SLOTS 8*2048 f | Rv,Cv 256 f | 8 mbarriers (64 B)
static constexpr int PF_FLOATS   = 16384;
static constexpr int SLOT_FLOATS = 2048;               // 32 rows x 64 cols
static constexpr int SLOTS_TOTAL = 8 * SLOT_FLOATS;    // 16384
static constexpr int SMEM_BYTES  = (PF_FLOATS + SLOTS_TOTAL + 256) * 4 + 64;

// swizzled float offset within a slot: row in [0,32), c4 = 16B block 0..15
__device__ __forceinline__ int slot_off(int row, int c4) {
    return row * 64 + (((c4) ^ (row & 7)) << 2);
}

__global__ void __launch_bounds__(256, 1)
fused_kernel(const float* __restrict__ x,
             const float* __restrict__ logits,
             const float* __restrict__ u,
             float* __restrict__ out, int ntiles) {
    extern __shared__ float sh[];
    float*  PF    = sh;
    float*  SLOTS = sh + PF_FLOATS;
    float*  Rv    = SLOTS + SLOTS_TOTAL;   // 128
    float*  Cv    = Rv + 128;              // 128
    float2* PF2   = reinterpret_cast<float2*>(PF);
    const uint32_t mbar_base = smem_u32(Cv + 128);  // 8 x 8B

    const int tid  = threadIdx.x;
    const int lane = tid & 31;
    const int wid  = tid >> 5;
    const int wm   = wid & 3;       // pair / band index: rows [wm*32, wm*32+32)
    const int wn   = wid >> 2;      // n-half: cols [wn*64, wn*64+64)
    const int pt   = (wn << 5) | lane;   // FIX: proper 0..63 within-pair index

    const uint32_t mb0 = mbar_base + wm * 16;
    const uint32_t mb1 = mb0 + 8;
    float* S0 = SLOTS + wm * 2 * SLOT_FLOATS;
    float* S1 = S0 + SLOT_FLOATS;

    if (tid < 8) mbar_init(mbar_base + tid * 8, 64u);

    // ================= sinkhorn prologue (proven 256-thread scheme) ==========
    {
        float* A = SLOTS;   // 16384-float scratch (slots region, pre-mainloop)
        for (int idx = tid; idx < 16384; idx += 256) {
            float uv = u[idx];
            float g  = -logf(-logf(uv + EPSF) + EPSF);
            float la = (logits[idx] + g) * (1.0f / 3.0f);
            la = fminf(10.0f, fmaxf(-10.0f, la));
            A[idx] = expf(la);
        }
        if (tid < 128) Cv[tid] = 1.0f;
        __syncthreads();

        const int i = tid >> 1;     // row/col 0..127
        const int s = tid & 1;      // half selector

        float4 a4[16];
        float  at[64];
#pragma unroll
        for (int k = 0; k < 16; k++)
            a4[k] = *reinterpret_cast<const float4*>(&A[i * 128 + s * 64 + k * 4]);
#pragma unroll
        for (int j = 0; j < 64; j++)
            at[j] = A[(s * 64 + j) * 128 + i];

        for (int it = 0; it < 20; it++) {
            float sum = 0.0f;
#pragma unroll
            for (int k = 0; k < 16; k++) {
                float4 cv = *reinterpret_cast<const float4*>(&Cv[s * 64 + k * 4]);
                sum += a4[k].x * cv.x + a4[k].y * cv.y + a4[k].z * cv.z + a4[k].w * cv.w;
            }
            sum += __shfl_xor_sync(0xffffffffu, sum, 1);
            if (s == 0) Rv[i] = 1.0f / sum;
            __syncthreads();

            float sum2 = 0.0f;
#pragma unroll
            for (int j = 0; j < 64; j += 4) {
                float4 rv = *reinterpret_cast<const float4*>(&Rv[s * 64 + j]);
                sum2 += at[j] * rv.x + at[j + 1] * rv.y + at[j + 2] * rv.z + at[j + 3] * rv.w;
            }
            sum2 += __shfl_xor_sync(0xffffffffu, sum2, 1);
            if (s == 0) Cv[i] = 1.0f / sum2;
            __syncthreads();
        }

        // P = diag(r) A diag(c) * (1+2^-11) [mma RZ-truncation compensation],
        // tf32-rounded, scattered into B-fragment order (proven layout).
        const float comp = 1.0f + 0.00048828125f;
        for (int idx = tid; idx < 16384; idx += 256) {
            int n = idx >> 7, k = idx & 127;
            float p = Rv[n] * A[n * 128 + k] * Cv[k] * comp;
            float pt32;
            asm("cvt.rna.tf32.f32 %0, %1;" : "=f"(pt32) : "f"(p));
            int ss = k >> 3, ko = k & 7;
            int fi = ((ss * 16 + (n >> 3)) * 32 + (n & 7) * 4 + (ko & 3)) * 2 + (ko >> 2);
            PF[fi] = pt32;
        }
        __syncthreads();   // PF ready, slots free, mbarriers visible. LAST CTA barrier.
    }

    // ================= per-pair streaming mainloop ============================
    const int grid = gridDim.x;
    int t0 = blockIdx.x;
    if (t0 >= ntiles) return;

    // slot fill: this thread copies 8 float4 of the pair's 32x64 k-half (KH)
#define ISSUE_CP(SLOT, T, KH)                                                    \
    {                                                                            \
        const float* srcb = x + ((size_t)(T) * 128 + wm * 32) * 128 + (KH) * 64; \
        _Pragma("unroll")                                                        \
        for (int i = 0; i < 8; i++) {                                            \
            int f   = i * 64 + pt;                                               \
            int row = f >> 4, c4 = f & 15;                                       \
            cp16((SLOT) + slot_off(row, c4), srcb + (size_t)row * 128 + c4 * 4); \
        }                                                                        \
    }

    // preload tile t0
    ISSUE_CP(S0, t0, 0); cp_arrive(mb0);
    ISSUE_CP(S1, t0, 1); cp_arrive(mb1);
    int ph0 = 0, ph1 = 0;

    const int barid = 1 + wm;

    for (int t = t0; t < ntiles; t += grid) {
        const bool more = (t + grid) < ntiles;

        float acc[2][8][4];
#pragma unroll
        for (int mf = 0; mf < 2; mf++)
#pragma unroll
            for (int nt = 0; nt < 8; nt++)
#pragma unroll
                for (int q = 0; q < 4; q++) acc[mf][nt][q] = 0.0f;

#define COMPUTE_HALF(SLOT, KH)                                                     \
        _Pragma("unroll")                                                          \
        for (int s8 = 0; s8 < 8; s8++) {                                           \
            int s = (KH) * 8 + s8;                                                 \
            float2 b[8];                                                           \
            _Pragma("unroll")                                                      \
            for (int nt = 0; nt < 8; nt++)                                         \
                b[nt] = PF2[(s * 16 + wn * 8 + nt) * 32 + lane];                   \
            _Pragma("unroll")                                                      \
            for (int mf = 0; mf < 2; mf++) {                                       \
                int rq = mf * 16 + (lane >> 2);                                    \
                int w4 = lane & 3;                                                 \
                int bc = s8 * 2;                                                   \
                uint32_t a0 = __float_as_uint((SLOT)[slot_off(rq,     bc    ) + w4]); \
                uint32_t a1 = __float_as_uint((SLOT)[slot_off(rq + 8, bc    ) + w4]); \
                uint32_t a2 = __float_as_uint((SLOT)[slot_off(rq,     bc + 1) + w4]); \
                uint32_t a3 = __float_as_uint((SLOT)[slot_off(rq + 8, bc + 1) + w4]); \
                _Pragma("unroll")                                                  \
                for (int nt = 0; nt < 8; nt++) {                                   \
                    asm volatile(                                                  \
                        "mma.sync.aligned.m16n8k8.row.col.f32.tf32.tf32.f32 "      \
                        "{%0,%1,%2,%3}, {%4,%5,%6,%7}, {%8,%9}, {%0,%1,%2,%3};"    \
                        : "+f"(acc[mf][nt][0]), "+f"(acc[mf][nt][1]),              \
                          "+f"(acc[mf][nt][2]), "+f"(acc[mf][nt][3])               \
                        : "r"(a0), "r"(a1), "r"(a2), "r"(a3),                      \
                          "r"(__float_as_uint(b[nt].x)),                           \
                          "r"(__float_as_uint(b[nt].y)));                          \
                }                                                                  \
            }                                                                      \
        }

        // ---- k-half 0 ----
        mbar_wait(mb0, ph0);
        COMPUTE_HALF(S0, 0)
        pair_bar(barid);                       // both pair warps done reading S0
        if (more) { ISSUE_CP(S0, t + grid, 0); cp_arrive(mb0); }
        ph0 ^= 1;

        // ---- k-half 1 ----
        mbar_wait(mb1, ph1);
        COMPUTE_HALF(S1, 1)
        pair_bar(barid);                       // both pair warps done reading S1
        if (more) { ISSUE_CP(S1, t + grid, 1); cp_arrive(mb1); }
        ph1 ^= 1;

#undef COMPUTE_HALF

        // ---- epilogue: direct STG.64 (each quad = one 32B sector) ----
        float2* og = reinterpret_cast<float2*>(out) + (size_t)t * 128 * 64;
#pragma unroll
        for (int mf = 0; mf < 2; mf++) {
            int r0 = wm * 32 + mf * 16 + (lane >> 2);
#pragma unroll
            for (int nt = 0; nt < 8; nt++) {
                int colp = wn * 32 + nt * 4 + (lane & 3);
                og[(size_t)r0 * 64 + colp]       = make_float2(acc[mf][nt][0], acc[mf][nt][1]);
                og[(size_t)(r0 + 8) * 64 + colp] = make_float2(acc[mf][nt][2], acc[mf][nt][3]);
            }
        }
    }
#undef ISSUE_CP
}

// ---------------------------------------------------------------------------
extern "C" void kernel_launch(void* const* d_in, const int* in_sizes, int n_in,
                              void* d_out, int out_size) {
    const float* x      = (const float*)d_in[0];
    const float* logits = (const float*)d_in[1];
    const float* u      = (const float*)d_in[2];
    float*       out    = (float*)d_out;

    int dev = 0, sms = 148;
    cudaGetDevice(&dev);
    cudaDeviceGetAttribute(&sms, cudaDevAttrMultiProcessorCount, dev);

    cudaFuncSetAttribute(fused_kernel, cudaFuncAttributeMaxDynamicSharedMemorySize, SMEM_BYTES);

    int rows   = in_sizes[0] / 128;   // 524288
    int ntiles = rows / 128;          // 4096
    fused_kernel<<<sms, 256, SMEM_BYTES>>>(x, logits, u, out, ntiles);
}